// round 7
// baseline (speedup 1.0000x reference)
#include <cuda_runtime.h>

// Net_90434831385322: z = LIM_A + span*sigmoid( relu(((x-LIM_A)/span) @ W1 + b1) @ W2 + b2 )
//
// R7 design (delta vs R5, which is the best passing kernel):
//  - PERSISTENT grid (296 CTAs): each warp loops ~9 iterations of 192 rows.
//    Removes per-wave launch/transition overhead (one body per warp in R5).
//  - Software pipeline: next iteration's 6 float4 x-loads are issued before the
//    current j-sweep, hiding DRAM latency behind ~770 cyc of FMA work.
//  - relu back to fmaxf-on-halves (max.f32x2 does not exist; R6 compile fail).
//  - Same core: folded scaling, fused layer2, dup'd u64 smem weights,
//    NPR=3 row-pairs/thread, coalesced warp-interleaved rows.

typedef unsigned long long u64;

__device__ __forceinline__ u64 ffma2(u64 a, u64 b, u64 c) {
    u64 d;
    asm("fma.rn.f32x2 %0, %1, %2, %3;" : "=l"(d) : "l"(a), "l"(b), "l"(c));
    return d;
}
__device__ __forceinline__ u64 pack2(float lo, float hi) {
    u64 d;
    asm("mov.b64 %0, {%1, %2};" : "=l"(d) : "f"(lo), "f"(hi));
    return d;
}
__device__ __forceinline__ void unpack2(u64 v, float& lo, float& hi) {
    asm("mov.b64 {%0, %1}, %2;" : "=f"(lo), "=f"(hi) : "l"(v));
}
__device__ __forceinline__ u64 relu2(u64 h) {
    float a, b;
    unpack2(h, a, b);
    a = fmaxf(a, 0.0f);
    b = fmaxf(b, 0.0f);
    return pack2(a, b);
}

#define HID 64
#define NPR 3              // row-pairs per thread (6 rows)
#define ROWS_PER_WARP 192  // 32 lanes * 6 rows

__global__ void __launch_bounds__(256, 2)
mlp_kernel(const float4* __restrict__ x,
           const float* __restrict__ W1,   // [4][64]
           const float* __restrict__ b1,   // [64]
           const float* __restrict__ W2,   // [64][4]
           const float* __restrict__ b2,   // [4]
           float4* __restrict__ out,
           int rows)
{
    __shared__ ulonglong2 sW[HID * 5];

    const int t = threadIdx.x;
    if (t < HID) {
        const float lim_a[4]    = {0.001f, 0.02f, 0.05f, 0.001f};
        const float inv_span[4] = {1.0f/0.003f, 1.0f/0.03f, 1.0f/0.15f, 1.0f/0.003f};
        const int j = t;
        float w[4];
        float bf = b1[j];
        #pragma unroll
        for (int i = 0; i < 4; i++) {
            w[i] = W1[i * HID + j] * inv_span[i];
            bf -= lim_a[i] * w[i];
        }
        float v2[4];
        #pragma unroll
        for (int k = 0; k < 4; k++) v2[k] = W2[j * 4 + k];

        sW[j * 5 + 0] = make_ulonglong2(pack2(w[0], w[0]), pack2(w[1], w[1]));
        sW[j * 5 + 1] = make_ulonglong2(pack2(w[2], w[2]), pack2(w[3], w[3]));
        sW[j * 5 + 2] = make_ulonglong2(pack2(v2[0], v2[0]), pack2(v2[1], v2[1]));
        sW[j * 5 + 3] = make_ulonglong2(pack2(v2[2], v2[2]), pack2(v2[3], v2[3]));
        sW[j * 5 + 4] = make_ulonglong2(pack2(bf, bf), 0ull);
    }
    __syncthreads();

    const float bb0 = b2[0], bb1 = b2[1], bb2 = b2[2], bb3 = b2[3];
    const float lim_a_k[4] = {0.001f, 0.02f, 0.05f, 0.001f};
    const float span_k[4]  = {0.003f, 0.03f, 0.15f, 0.003f};

    const int lane = t & 31;
    const int warp = t >> 5;
    const int warpsPerBlock = blockDim.x >> 5;
    const int gwarp  = blockIdx.x * warpsPerBlock + warp;
    const int nwarps = gridDim.x * warpsPerBlock;
    const int stride = nwarps * ROWS_PER_WARP;

    int iterBase = gwarp * ROWS_PER_WARP;
    if (iterBase >= rows) return;

    // ---- preload first iteration's rows ----
    float4 xr[2 * NPR];
    {
        const bool full = (iterBase + ROWS_PER_WARP) <= rows;
        #pragma unroll
        for (int i = 0; i < 2 * NPR; i++) {
            int r = iterBase + lane + 32 * i;
            if (!full) r = r < rows ? r : (rows - 1);
            xr[i] = x[r];
        }
    }

    for (; iterBase < rows; iterBase += stride) {
        const int nextBase = iterBase + stride;
        const bool hasNext = nextBase < rows;

        // ---- prefetch next iteration's rows (overlaps with j-sweep) ----
        float4 xn[2 * NPR];
        if (hasNext) {
            const bool nfull = (nextBase + ROWS_PER_WARP) <= rows;
            #pragma unroll
            for (int i = 0; i < 2 * NPR; i++) {
                int r = nextBase + lane + 32 * i;
                if (!nfull) r = r < rows ? r : (rows - 1);
                xn[i] = x[r];
            }
        }

        // ---- pack current rows into row-pair u64s ----
        u64 xp[NPR][4];
        #pragma unroll
        for (int pr = 0; pr < NPR; pr++) {
            const float4 a = xr[2 * pr];
            const float4 b = xr[2 * pr + 1];
            xp[pr][0] = pack2(a.x, b.x);
            xp[pr][1] = pack2(a.y, b.y);
            xp[pr][2] = pack2(a.z, b.z);
            xp[pr][3] = pack2(a.w, b.w);
        }

        // ---- accumulators ----
        u64 y[NPR][4];
        #pragma unroll
        for (int pr = 0; pr < NPR; pr++) {
            y[pr][0] = pack2(bb0, bb0);
            y[pr][1] = pack2(bb1, bb1);
            y[pr][2] = pack2(bb2, bb2);
            y[pr][3] = pack2(bb3, bb3);
        }

        // ---- fused layer1 + relu + layer2 over 64 hidden units ----
        #pragma unroll 16
        for (int j = 0; j < HID; j++) {
            const ulonglong2 wA = sW[j * 5 + 0];
            const ulonglong2 wB = sW[j * 5 + 1];
            const ulonglong2 wC = sW[j * 5 + 2];
            const ulonglong2 wD = sW[j * 5 + 3];
            const u64 b1d = sW[j * 5 + 4].x;

            #pragma unroll
            for (int pr = 0; pr < NPR; pr++) {
                u64 h = ffma2(xp[pr][0], wA.x, b1d);
                h = ffma2(xp[pr][1], wA.y, h);
                h = ffma2(xp[pr][2], wB.x, h);
                h = ffma2(xp[pr][3], wB.y, h);
                h = relu2(h);
                y[pr][0] = ffma2(h, wC.x, y[pr][0]);
                y[pr][1] = ffma2(h, wC.y, y[pr][1]);
                y[pr][2] = ffma2(h, wD.x, y[pr][2]);
                y[pr][3] = ffma2(h, wD.y, y[pr][3]);
            }
        }

        // ---- sigmoid epilogue + coalesced stores ----
        const bool full = (iterBase + ROWS_PER_WARP) <= rows;
        #pragma unroll
        for (int pr = 0; pr < NPR; pr++) {
            float4 o0, o1;
            float* p0 = &o0.x;
            float* p1 = &o1.x;
            #pragma unroll
            for (int k = 0; k < 4; k++) {
                float ya, yb;
                unpack2(y[pr][k], ya, yb);
                const float s0 = __fdividef(1.0f, 1.0f + __expf(-ya));
                const float s1 = __fdividef(1.0f, 1.0f + __expf(-yb));
                p0[k] = fmaf(span_k[k], s0, lim_a_k[k]);
                p1[k] = fmaf(span_k[k], s1, lim_a_k[k]);
            }
            const int r0 = iterBase + lane + 32 * (2 * pr);
            const int r1 = r0 + 32;
            if (full) {
                out[r0] = o0;
                out[r1] = o1;
            } else {
                if (r0 < rows) out[r0] = o0;
                if (r1 < rows) out[r1] = o1;
            }
        }

        // ---- rotate prefetched rows in ----
        if (hasNext) {
            #pragma unroll
            for (int i = 0; i < 2 * NPR; i++) xr[i] = xn[i];
        }
    }
}

extern "C" void kernel_launch(void* const* d_in, const int* in_sizes, int n_in,
                              void* d_out, int out_size) {
    const float* x  = (const float*)d_in[0];
    const float* W1 = (const float*)d_in[1];
    const float* b1 = (const float*)d_in[2];
    const float* W2 = (const float*)d_in[3];
    const float* b2 = (const float*)d_in[4];
    const int rows = in_sizes[0] / 4;

    const int threads = 256;
    int blocks = 296;  // 148 SMs * 2 CTAs/SM, persistent
    // never launch more CTAs than needed
    const int rowsPerBlock = (threads / 32) * ROWS_PER_WARP;  // 1536
    const int needed = (rows + rowsPerBlock - 1) / rowsPerBlock;
    if (needed < blocks) blocks = needed;

    mlp_kernel<<<blocks, threads>>>(
        (const float4*)x, W1, b1, W2, b2, (float4*)d_out, rows);
}

// round 8
// speedup vs baseline: 1.1430x; 1.1430x over previous
#include <cuda_runtime.h>

// Net_90434831385322: z = LIM_A + span*sigmoid( relu(((x-LIM_A)/span) @ W1 + b1) @ W2 + b2 )
//
// R8 design (delta vs R5 best):
//  - f32x2 lanes repacked over HIDDEN-UNIT PAIRS (j, j+1) instead of row pairs.
//    Weight pairs are adjacent values -> NO duplication in smem -> LDS per
//    hidden unit drops 5 -> 2.5 (4x LDS.128 + 1x LDS.64 per j-pair).
//    x is duplicated into both lanes once per row (4 u64, prologue).
//  - Layer2 accumulators y[k] keep (partial_j_even, partial_j_odd); merged with
//    one add in the epilogue.
//  - 4 rows per thread, warp-interleaved coalesced rows, non-persistent grid
//    (R7 persistence regressed).

typedef unsigned long long u64;

__device__ __forceinline__ u64 ffma2(u64 a, u64 b, u64 c) {
    u64 d;
    asm("fma.rn.f32x2 %0, %1, %2, %3;" : "=l"(d) : "l"(a), "l"(b), "l"(c));
    return d;
}
__device__ __forceinline__ u64 pack2(float lo, float hi) {
    u64 d;
    asm("mov.b64 %0, {%1, %2};" : "=l"(d) : "f"(lo), "f"(hi));
    return d;
}
__device__ __forceinline__ void unpack2(u64 v, float& lo, float& hi) {
    asm("mov.b64 {%0, %1}, %2;" : "=f"(lo), "=f"(hi) : "l"(v));
}
__device__ __forceinline__ u64 relu2(u64 h) {
    float a, b;
    unpack2(h, a, b);
    a = fmaxf(a, 0.0f);
    b = fmaxf(b, 0.0f);
    return pack2(a, b);
}

#define HID 64
#define NJP 32             // hidden-unit pairs
#define NR 4               // rows per thread
#define ROWS_PER_WARP 128  // 32 lanes * 4 rows

// Shared layout per j-pair jp (hidden units j=2jp, j+1):
//  sA[jp] = ((W1f[0][j],W1f[0][j+1]), (W1f[1][j],W1f[1][j+1]))   ulonglong2
//  sB[jp] = ((W1f[2][j],W1f[2][j+1]), (W1f[3][j],W1f[3][j+1]))
//  sC[jp] = ((W2[j][0], W2[j+1][0]),  (W2[j][1], W2[j+1][1]))
//  sD[jp] = ((W2[j][2], W2[j+1][2]),  (W2[j][3], W2[j+1][3]))
//  sE[jp] = (b1f[j], b1f[j+1])                                    u64
__global__ void __launch_bounds__(256, 2)
mlp_kernel(const float4* __restrict__ x,
           const float* __restrict__ W1,   // [4][64]
           const float* __restrict__ b1,   // [64]
           const float* __restrict__ W2,   // [64][4]
           const float* __restrict__ b2,   // [4]
           float4* __restrict__ out,
           int rows)
{
    __shared__ ulonglong2 sA[NJP];
    __shared__ ulonglong2 sB[NJP];
    __shared__ ulonglong2 sC[NJP];
    __shared__ ulonglong2 sD[NJP];
    __shared__ u64        sE[NJP];

    const int t = threadIdx.x;
    if (t < NJP) {
        const float lim_a[4]    = {0.001f, 0.02f, 0.05f, 0.001f};
        const float inv_span[4] = {1.0f/0.003f, 1.0f/0.03f, 1.0f/0.15f, 1.0f/0.003f};
        const int jp = t;
        const int j0 = 2 * jp, j1 = 2 * jp + 1;
        float w0[4], w1[4];
        float bf0 = b1[j0], bf1 = b1[j1];
        #pragma unroll
        for (int i = 0; i < 4; i++) {
            w0[i] = W1[i * HID + j0] * inv_span[i];
            w1[i] = W1[i * HID + j1] * inv_span[i];
            bf0 -= lim_a[i] * w0[i];
            bf1 -= lim_a[i] * w1[i];
        }
        sA[jp] = make_ulonglong2(pack2(w0[0], w1[0]), pack2(w0[1], w1[1]));
        sB[jp] = make_ulonglong2(pack2(w0[2], w1[2]), pack2(w0[3], w1[3]));
        sC[jp] = make_ulonglong2(pack2(W2[j0*4+0], W2[j1*4+0]),
                                 pack2(W2[j0*4+1], W2[j1*4+1]));
        sD[jp] = make_ulonglong2(pack2(W2[j0*4+2], W2[j1*4+2]),
                                 pack2(W2[j0*4+3], W2[j1*4+3]));
        sE[jp] = pack2(bf0, bf1);
    }
    __syncthreads();

    const float bb0 = b2[0], bb1 = b2[1], bb2 = b2[2], bb3 = b2[3];
    const float lim_a_k[4] = {0.001f, 0.02f, 0.05f, 0.001f};
    const float span_k[4]  = {0.003f, 0.03f, 0.15f, 0.003f};

    const int lane = t & 31;
    const int warp = t >> 5;
    const int warpsPerBlock = blockDim.x >> 5;
    const int base = (blockIdx.x * warpsPerBlock + warp) * ROWS_PER_WARP + lane;

    const bool full = (base + 32 * (NR - 1)) < rows;

    // ---- load NR rows, duplicate each x_i into both lanes ----
    u64 xd[NR][4];
    #pragma unroll
    for (int rr = 0; rr < NR; rr++) {
        int r = base + 32 * rr;
        if (!full) r = r < rows ? r : (rows - 1);
        const float4 a = x[r];
        xd[rr][0] = pack2(a.x, a.x);
        xd[rr][1] = pack2(a.y, a.y);
        xd[rr][2] = pack2(a.z, a.z);
        xd[rr][3] = pack2(a.w, a.w);
    }

    // ---- accumulators: y[rr][k] = (partial over even j, partial over odd j) ----
    u64 y[NR][4];
    #pragma unroll
    for (int rr = 0; rr < NR; rr++) {
        y[rr][0] = 0ull;
        y[rr][1] = 0ull;
        y[rr][2] = 0ull;
        y[rr][3] = 0ull;
    }

    // ---- fused layer1 + relu + layer2 over 32 hidden-unit pairs ----
    #pragma unroll 8
    for (int jp = 0; jp < NJP; jp++) {
        const ulonglong2 wA = sA[jp];
        const ulonglong2 wB = sB[jp];
        const ulonglong2 wC = sC[jp];
        const ulonglong2 wD = sD[jp];
        const u64 b1d = sE[jp];

        #pragma unroll
        for (int rr = 0; rr < NR; rr++) {
            u64 h = ffma2(xd[rr][0], wA.x, b1d);
            h = ffma2(xd[rr][1], wA.y, h);
            h = ffma2(xd[rr][2], wB.x, h);
            h = ffma2(xd[rr][3], wB.y, h);
            h = relu2(h);   // (h_j, h_j+1) for this row
            y[rr][0] = ffma2(h, wC.x, y[rr][0]);
            y[rr][1] = ffma2(h, wC.y, y[rr][1]);
            y[rr][2] = ffma2(h, wD.x, y[rr][2]);
            y[rr][3] = ffma2(h, wD.y, y[rr][3]);
        }
    }

    // ---- merge lane partials, sigmoid, store ----
    #pragma unroll
    for (int rr = 0; rr < NR; rr++) {
        float4 o;
        float* p = &o.x;
        const float bbk[4] = {bb0, bb1, bb2, bb3};
        #pragma unroll
        for (int k = 0; k < 4; k++) {
            float ye, yo;
            unpack2(y[rr][k], ye, yo);
            const float yk = ye + yo + bbk[k];
            const float s = __fdividef(1.0f, 1.0f + __expf(-yk));
            p[k] = fmaf(span_k[k], s, lim_a_k[k]);
        }
        const int r = base + 32 * rr;
        if (full) {
            out[r] = o;
        } else {
            if (r < rows) out[r] = o;
        }
    }
}

extern "C" void kernel_launch(void* const* d_in, const int* in_sizes, int n_in,
                              void* d_out, int out_size) {
    const float* x  = (const float*)d_in[0];
    const float* W1 = (const float*)d_in[1];
    const float* b1 = (const float*)d_in[2];
    const float* W2 = (const float*)d_in[3];
    const float* b2 = (const float*)d_in[4];
    const int rows = in_sizes[0] / 4;

    const int threads = 256;
    const int rowsPerBlock = (threads / 32) * ROWS_PER_WARP;  // 1024
    const int blocks = (rows + rowsPerBlock - 1) / rowsPerBlock;  // 4096
    mlp_kernel<<<blocks, threads>>>(
        (const float4*)x, W1, b1, W2, b2, (float4*)d_out, rows);
}

// round 9
// speedup vs baseline: 1.4578x; 1.2754x over previous
#include <cuda_runtime.h>

// Net_90434831385322: z = LIM_A + span*sigmoid( relu(((x-LIM_A)/span) @ W1 + b1) @ W2 + b2 )
//
// R9 design (delta vs R8 best):
//  - Weights moved from shared memory to __constant__ memory. Weights are
//    warp-uniform; const-path loads (LDC/LDCU->UR) let ffma2 take its B operand
//    from the uniform register file, cutting GPR bank reads per ffma2 from
//    3even+3odd (rt=3, the R4-R8 plateau) to 2+2 (rt=2).
//  - Setup kernel folds input scaling into W1/b1 and packs the j-pair layout
//    into a __device__ global; cudaMemcpyToSymbolAsync D2D (graph-legal) moves
//    it into __constant__ before the main kernel.
//  - Main kernel: identical j-pair f32x2 structure as R8 (4 rows/thread,
//    warp-interleaved coalesced rows), but zero smem, zero __syncthreads.

typedef unsigned long long u64;

__device__ __forceinline__ u64 ffma2(u64 a, u64 b, u64 c) {
    u64 d;
    asm("fma.rn.f32x2 %0, %1, %2, %3;" : "=l"(d) : "l"(a), "l"(b), "l"(c));
    return d;
}
__device__ __forceinline__ u64 pack2(float lo, float hi) {
    u64 d;
    asm("mov.b64 %0, {%1, %2};" : "=l"(d) : "f"(lo), "f"(hi));
    return d;
}
__device__ __forceinline__ void unpack2(u64 v, float& lo, float& hi) {
    asm("mov.b64 {%0, %1}, %2;" : "=f"(lo), "=f"(hi) : "l"(v));
}
__device__ __forceinline__ u64 relu2(u64 h) {
    float a, b;
    unpack2(h, a, b);
    a = fmaxf(a, 0.0f);
    b = fmaxf(b, 0.0f);
    return pack2(a, b);
}

#define HID 64
#define NJP 32             // hidden-unit pairs
#define NR 4               // rows per thread
#define ROWS_PER_WARP 128  // 32 lanes * 4 rows

// Folded weights, j-pair layout (see R8):
//  A[jp] = ((W1f[0][j],W1f[0][j+1]), (W1f[1][j],W1f[1][j+1]))
//  B[jp] = ((W1f[2][j],W1f[2][j+1]), (W1f[3][j],W1f[3][j+1]))
//  C[jp] = ((W2[j][0], W2[j+1][0]),  (W2[j][1], W2[j+1][1]))
//  D[jp] = ((W2[j][2], W2[j+1][2]),  (W2[j][3], W2[j+1][3]))
//  E[jp] = (b1f[j], b1f[j+1])
struct Fold {
    ulonglong2 A[NJP];
    ulonglong2 B[NJP];
    ulonglong2 C[NJP];
    ulonglong2 D[NJP];
    u64        E[NJP];
    float      bb[4];
};

__device__    Fold gFold;   // staging (written by setup kernel)
__constant__  Fold cFold;   // read by main kernel via const path

__global__ void fold_kernel(const float* __restrict__ W1,   // [4][64]
                            const float* __restrict__ b1,   // [64]
                            const float* __restrict__ W2,   // [64][4]
                            const float* __restrict__ b2)   // [4]
{
    const int jp = threadIdx.x;
    if (jp < NJP) {
        const float lim_a[4]    = {0.001f, 0.02f, 0.05f, 0.001f};
        const float inv_span[4] = {1.0f/0.003f, 1.0f/0.03f, 1.0f/0.15f, 1.0f/0.003f};
        const int j0 = 2 * jp, j1 = 2 * jp + 1;
        float w0[4], w1[4];
        float bf0 = b1[j0], bf1 = b1[j1];
        #pragma unroll
        for (int i = 0; i < 4; i++) {
            w0[i] = W1[i * HID + j0] * inv_span[i];
            w1[i] = W1[i * HID + j1] * inv_span[i];
            bf0 -= lim_a[i] * w0[i];
            bf1 -= lim_a[i] * w1[i];
        }
        gFold.A[jp] = make_ulonglong2(pack2(w0[0], w1[0]), pack2(w0[1], w1[1]));
        gFold.B[jp] = make_ulonglong2(pack2(w0[2], w1[2]), pack2(w0[3], w1[3]));
        gFold.C[jp] = make_ulonglong2(pack2(W2[j0*4+0], W2[j1*4+0]),
                                      pack2(W2[j0*4+1], W2[j1*4+1]));
        gFold.D[jp] = make_ulonglong2(pack2(W2[j0*4+2], W2[j1*4+2]),
                                      pack2(W2[j0*4+3], W2[j1*4+3]));
        gFold.E[jp] = pack2(bf0, bf1);
        if (jp < 4) gFold.bb[jp] = b2[jp];
    }
}

__global__ void __launch_bounds__(256, 2)
mlp_kernel(const float4* __restrict__ x,
           float4* __restrict__ out,
           int rows)
{
    const int t = threadIdx.x;
    const int lane = t & 31;
    const int warp = t >> 5;
    const int warpsPerBlock = blockDim.x >> 5;
    const int base = (blockIdx.x * warpsPerBlock + warp) * ROWS_PER_WARP + lane;

    const bool full = (base + 32 * (NR - 1)) < rows;

    // ---- load NR rows, duplicate each x_i into both lanes ----
    u64 xd[NR][4];
    #pragma unroll
    for (int rr = 0; rr < NR; rr++) {
        int r = base + 32 * rr;
        if (!full) r = r < rows ? r : (rows - 1);
        const float4 a = x[r];
        xd[rr][0] = pack2(a.x, a.x);
        xd[rr][1] = pack2(a.y, a.y);
        xd[rr][2] = pack2(a.z, a.z);
        xd[rr][3] = pack2(a.w, a.w);
    }

    // ---- accumulators: y[rr][k] = (partial over even j, partial over odd j) ----
    u64 y[NR][4];
    #pragma unroll
    for (int rr = 0; rr < NR; rr++) {
        y[rr][0] = 0ull;
        y[rr][1] = 0ull;
        y[rr][2] = 0ull;
        y[rr][3] = 0ull;
    }

    // ---- fused layer1 + relu + layer2 over 32 hidden-unit pairs ----
    #pragma unroll 8
    for (int jp = 0; jp < NJP; jp++) {
        const ulonglong2 wA = cFold.A[jp];
        const ulonglong2 wB = cFold.B[jp];
        const ulonglong2 wC = cFold.C[jp];
        const ulonglong2 wD = cFold.D[jp];
        const u64 b1d = cFold.E[jp];

        #pragma unroll
        for (int rr = 0; rr < NR; rr++) {
            u64 h = ffma2(xd[rr][0], wA.x, b1d);
            h = ffma2(xd[rr][1], wA.y, h);
            h = ffma2(xd[rr][2], wB.x, h);
            h = ffma2(xd[rr][3], wB.y, h);
            h = relu2(h);   // (h_j, h_j+1) for this row
            y[rr][0] = ffma2(h, wC.x, y[rr][0]);
            y[rr][1] = ffma2(h, wC.y, y[rr][1]);
            y[rr][2] = ffma2(h, wD.x, y[rr][2]);
            y[rr][3] = ffma2(h, wD.y, y[rr][3]);
        }
    }

    // ---- merge lane partials, sigmoid, store ----
    const float lim_a_k[4] = {0.001f, 0.02f, 0.05f, 0.001f};
    const float span_k[4]  = {0.003f, 0.03f, 0.15f, 0.003f};

    #pragma unroll
    for (int rr = 0; rr < NR; rr++) {
        float4 o;
        float* p = &o.x;
        #pragma unroll
        for (int k = 0; k < 4; k++) {
            float ye, yo;
            unpack2(y[rr][k], ye, yo);
            const float yk = ye + yo + cFold.bb[k];
            const float s = __fdividef(1.0f, 1.0f + __expf(-yk));
            p[k] = fmaf(span_k[k], s, lim_a_k[k]);
        }
        const int r = base + 32 * rr;
        if (full) {
            out[r] = o;
        } else {
            if (r < rows) out[r] = o;
        }
    }
}

extern "C" void kernel_launch(void* const* d_in, const int* in_sizes, int n_in,
                              void* d_out, int out_size) {
    const float* x  = (const float*)d_in[0];
    const float* W1 = (const float*)d_in[1];
    const float* b1 = (const float*)d_in[2];
    const float* W2 = (const float*)d_in[3];
    const float* b2 = (const float*)d_in[4];
    const int rows = in_sizes[0] / 4;

    // 1) fold weights into staging global
    fold_kernel<<<1, 32>>>(W1, b1, W2, b2);

    // 2) D2D copy into __constant__ (graph-capturable memcpy node)
    void* gptr = nullptr;
    cudaGetSymbolAddress(&gptr, gFold);
    cudaMemcpyToSymbolAsync(cFold, gptr, sizeof(Fold), 0,
                            cudaMemcpyDeviceToDevice);

    // 3) main kernel
    const int threads = 256;
    const int rowsPerBlock = (threads / 32) * ROWS_PER_WARP;  // 1024
    const int blocks = (rows + rowsPerBlock - 1) / rowsPerBlock;  // 4096
    mlp_kernel<<<blocks, threads>>>((const float4*)x, (float4*)d_out, rows);
}